// round 3
// baseline (speedup 1.0000x reference)
#include <cuda_runtime.h>

#define CDIM 3755
#define RDIM 214
#define SDIM 13
#define SCBDIM 30
#define STDIM 6
#define HDIM 64
#define KTOP 20
#define CAP 128
#define WPB 8
#define NT (WPB * 32)
#define NEGF 3.4e38f

__device__ __forceinline__ unsigned f2key(float x) {
    unsigned u = __float_as_uint(x);
    return (u & 0x80000000u) ? ~u : (u | 0x80000000u);
}
__device__ __forceinline__ float key2f(unsigned k) {
    return __uint_as_float((k & 0x80000000u) ? (k & 0x7FFFFFFFu) : ~k);
}
__device__ __forceinline__ unsigned long long packvi(float v, int j) {
    return ((unsigned long long)f2key(v) << 32) | (unsigned)(0x7FFFFFFF - j);
}

__global__ void __launch_bounds__(NT) rerank_kernel(
    const float* __restrict__ charL,   // (B, C)
    const float* __restrict__ radL,    // (B, R)
    const float* __restrict__ structL, // (B, S)
    const float* __restrict__ scL,     // (B, SCB)
    const float* __restrict__ styL,    // (B, ST)
    const int*   __restrict__ rmask,   // (C, R)
    const int*   __restrict__ slab,    // (C,)
    const int*   __restrict__ sclab,   // (C,)
    const float* __restrict__ sig,     // (C, ST)
    const float* __restrict__ W1,      // (6, H)
    const float* __restrict__ b1,      // (H,)
    const float* __restrict__ W2,      // (H, 1)
    const float* __restrict__ b2,      // (1,)
    const float* __restrict__ rwp,     // scalar
    float* __restrict__ out,           // (B, C)
    int Brows)
{
    __shared__ float w1s[6 * HDIM], b1sh[HDIM], w2sh[HDIM], s_misc[2];
    __shared__ unsigned long long cpack[WPB][CAP];
    __shared__ float rps[WPB][RDIM];
    __shared__ int   tIdx[WPB][KTOP];
    __shared__ float tVal[WPB][KTOP];
    __shared__ float f01[WPB][KTOP][2];
    __shared__ float sprob[WPB][SDIM];
    __shared__ float predn[WPB][STDIM];

    const int tid = threadIdx.x, lane = tid & 31, wid = tid >> 5;

    for (int i = tid; i < 6 * HDIM; i += NT) w1s[i] = W1[i];
    if (tid < HDIM) { b1sh[tid] = b1[tid]; w2sh[tid] = W2[tid]; }
    if (tid == 0) { s_misc[0] = b2[0]; s_misc[1] = rwp[0]; }
    __syncthreads();

    const int b = blockIdx.x * WPB + wid;
    if (b >= Brows) return;

    const float* row = charL + (size_t)b * CDIM;
    const int mis = ((int)((size_t)row & 15)) >> 2;
    const int h = (4 - mis) & 3;
    const int nv = (CDIM - h) >> 2;
    const int tl = CDIM - h - 4 * nv;
    const float4* r4 = (const float4*)(row + h);
    float* orow = out + (size_t)b * CDIM;
    float4* o4 = (float4*)(orow + h);

    // ---- pass 1: row max ----
    float mx = -NEGF;
    if (lane < h) mx = fmaxf(mx, row[lane]);
    for (int base = 0; base < nv; base += 32) {
        int i = base + lane;
        if (i < nv) {
            float4 v = r4[i];
            mx = fmaxf(mx, fmaxf(fmaxf(v.x, v.y), fmaxf(v.z, v.w)));
        }
    }
    if (lane < tl) mx = fmaxf(mx, row[h + 4 * nv + lane]);
    #pragma unroll
    for (int o = 16; o; o >>= 1) mx = fmaxf(mx, __shfl_xor_sync(~0u, mx, o));
    const float rowmax = mx;

    // ---- radical sigmoid + total ----
    float tp = 0.f;
    for (int r = lane; r < RDIM; r += 32) {
        float p = 1.f / (1.f + __expf(-radL[(size_t)b * RDIM + r]));
        rps[wid][r] = p;
        tp += p;
    }
    #pragma unroll
    for (int o = 16; o; o >>= 1) tp += __shfl_xor_sync(~0u, tp, o);
    const float total = tp;

    // ---- structure softmax (lanes 0..12) ----
    {
        float sv = (lane < SDIM) ? structL[(size_t)b * SDIM + lane] : -NEGF;
        float sm = sv;
        #pragma unroll
        for (int o = 16; o; o >>= 1) sm = fmaxf(sm, __shfl_xor_sync(~0u, sm, o));
        float e = (lane < SDIM) ? __expf(sv - sm) : 0.f;
        float ss = e;
        #pragma unroll
        for (int o = 16; o; o >>= 1) ss += __shfl_xor_sync(~0u, ss, o);
        if (lane < SDIM) sprob[wid][lane] = e / ss;
    }
    // ---- stroke-count argmax (first max wins) ----
    int sp;
    {
        unsigned long long p = 0ull;
        if (lane < SCBDIM) {
            float v = scL[(size_t)b * SCBDIM + lane];
            p = ((unsigned long long)f2key(v) << 32) | (unsigned)(31 - lane);
        }
        #pragma unroll
        for (int o = 16; o; o >>= 1) {
            unsigned long long q = __shfl_xor_sync(~0u, p, o);
            if (q > p) p = q;
        }
        sp = 31 - (int)(p & 0xFFFFFFFFu);
    }
    // ---- normalized stroke-type prediction ----
    {
        float v = (lane < STDIM) ? styL[(size_t)b * STDIM + lane] : 0.f;
        float n2 = v * v;
        #pragma unroll
        for (int o = 16; o; o >>= 1) n2 += __shfl_xor_sync(~0u, n2, o);
        float n = fmaxf(sqrtf(n2), 1e-12f);
        if (lane < STDIM) predn[wid][lane] = v / n;
    }

    // ---- pass 2 (fused): expsum + copy-out + threshold collect ----
    const unsigned lm = (1u << lane) - 1u;
    float dlt = 1.4f;
    float t = rowmax - dlt;
    int nc = 0;
    float se = 0.f;
    {
        float v = (lane < h) ? row[lane] : -NEGF;
        se += __expf(v - rowmax);
        if (lane < h) orow[lane] = v;
        bool pr = v >= t;
        unsigned m0 = __ballot_sync(~0u, pr);
        if (m0) {
            int pos = nc + __popc(m0 & lm);
            if (pr && pos < CAP) cpack[wid][pos] = packvi(v, lane);
            nc += __popc(m0);
        }
    }
    for (int base = 0; base < nv; base += 32) {
        int i = base + lane;
        bool act = i < nv;
        float4 v;
        if (act) v = r4[i]; else { v.x = v.y = v.z = v.w = -NEGF; }
        se += __expf(v.x - rowmax) + __expf(v.y - rowmax)
            + __expf(v.z - rowmax) + __expf(v.w - rowmax);
        if (act) o4[i] = v;
        bool p0 = v.x >= t, p1 = v.y >= t, p2 = v.z >= t, p3 = v.w >= t;
        unsigned any = __ballot_sync(~0u, p0 | p1 | p2 | p3);
        if (any) {
            int j0 = h + 4 * i;
            unsigned m0 = __ballot_sync(~0u, p0);
            if (p0) { int pos = nc + __popc(m0 & lm); if (pos < CAP) cpack[wid][pos] = packvi(v.x, j0); }
            nc += __popc(m0);
            unsigned m1 = __ballot_sync(~0u, p1);
            if (p1) { int pos = nc + __popc(m1 & lm); if (pos < CAP) cpack[wid][pos] = packvi(v.y, j0 + 1); }
            nc += __popc(m1);
            unsigned m2 = __ballot_sync(~0u, p2);
            if (p2) { int pos = nc + __popc(m2 & lm); if (pos < CAP) cpack[wid][pos] = packvi(v.z, j0 + 2); }
            nc += __popc(m2);
            unsigned m3 = __ballot_sync(~0u, p3);
            if (p3) { int pos = nc + __popc(m3 & lm); if (pos < CAP) cpack[wid][pos] = packvi(v.w, j0 + 3); }
            nc += __popc(m3);
        }
    }
    {
        int j = h + 4 * nv + lane;
        float v = (lane < tl) ? row[j] : -NEGF;
        se += __expf(v - rowmax);
        if (lane < tl) orow[j] = v;
        bool pr = v >= t;
        unsigned m0 = __ballot_sync(~0u, pr);
        if (m0) {
            int pos = nc + __popc(m0 & lm);
            if (pr && pos < CAP) cpack[wid][pos] = packvi(v, j);
            nc += __popc(m0);
        }
    }
    #pragma unroll
    for (int o = 16; o; o >>= 1) se += __shfl_xor_sync(~0u, se, o);
    const float inv_sum = 1.f / se;

    // ---- retry with looser threshold (rare) ----
    while (nc < KTOP) {
        dlt *= 2.f;
        t = rowmax - dlt;
        nc = 0;
        {
            float v = (lane < h) ? row[lane] : -NEGF;
            bool pr = v >= t;
            unsigned m0 = __ballot_sync(~0u, pr);
            if (m0) { int pos = nc + __popc(m0 & lm); if (pr && pos < CAP) cpack[wid][pos] = packvi(v, lane); nc += __popc(m0); }
        }
        for (int base = 0; base < nv; base += 32) {
            int i = base + lane;
            bool act = i < nv;
            float4 v;
            if (act) v = r4[i]; else { v.x = v.y = v.z = v.w = -NEGF; }
            bool p0 = v.x >= t, p1 = v.y >= t, p2 = v.z >= t, p3 = v.w >= t;
            unsigned any = __ballot_sync(~0u, p0 | p1 | p2 | p3);
            if (any) {
                int j0 = h + 4 * i;
                unsigned m0 = __ballot_sync(~0u, p0);
                if (p0) { int pos = nc + __popc(m0 & lm); if (pos < CAP) cpack[wid][pos] = packvi(v.x, j0); }
                nc += __popc(m0);
                unsigned m1 = __ballot_sync(~0u, p1);
                if (p1) { int pos = nc + __popc(m1 & lm); if (pos < CAP) cpack[wid][pos] = packvi(v.y, j0 + 1); }
                nc += __popc(m1);
                unsigned m2 = __ballot_sync(~0u, p2);
                if (p2) { int pos = nc + __popc(m2 & lm); if (pos < CAP) cpack[wid][pos] = packvi(v.z, j0 + 2); }
                nc += __popc(m2);
                unsigned m3 = __ballot_sync(~0u, p3);
                if (p3) { int pos = nc + __popc(m3 & lm); if (pos < CAP) cpack[wid][pos] = packvi(v.w, j0 + 3); }
                nc += __popc(m3);
            }
        }
        {
            int j = h + 4 * nv + lane;
            float v = (lane < tl) ? row[j] : -NEGF;
            bool pr = v >= t;
            unsigned m0 = __ballot_sync(~0u, pr);
            if (m0) { int pos = nc + __popc(m0 & lm); if (pr && pos < CAP) cpack[wid][pos] = packvi(v, j); nc += __popc(m0); }
        }
    }

    // ---- selection ----
    __syncwarp();
    if (nc <= CAP) {
        // rank-based exact top-K (ties: lower index first, encoded in pack)
        unsigned long long myp[4]; int rk[4];
        #pragma unroll
        for (int m = 0; m < 4; m++) {
            int q = m * 32 + lane;
            myp[m] = (q < nc) ? cpack[wid][q] : 0ull;
            rk[m] = 0;
        }
        for (int j = 0; j < nc; j++) {
            unsigned long long p = cpack[wid][j];
            #pragma unroll
            for (int m = 0; m < 4; m++) rk[m] += (p > myp[m]);
        }
        #pragma unroll
        for (int m = 0; m < 4; m++) {
            int q = m * 32 + lane;
            if (q < nc && rk[m] < KTOP) {
                tIdx[wid][rk[m]] = 0x7FFFFFFF - (int)(myp[m] & 0xFFFFFFFFu);
                tVal[wid][rk[m]] = key2f((unsigned)(myp[m] >> 32));
            }
        }
    } else {
        // robust fallback: 20 rounds of warp argmax over the row (adversarial only)
        unsigned long long prev = ~0ull;
        for (int k = 0; k < KTOP; k++) {
            unsigned long long best = 0ull;
            if (lane < h) { unsigned long long p = packvi(row[lane], lane); if (p < prev && p > best) best = p; }
            for (int base = 0; base < nv; base += 32) {
                int i = base + lane;
                if (i < nv) {
                    float4 v = r4[i]; int j0 = h + 4 * i;
                    unsigned long long p;
                    p = packvi(v.x, j0);     if (p < prev && p > best) best = p;
                    p = packvi(v.y, j0 + 1); if (p < prev && p > best) best = p;
                    p = packvi(v.z, j0 + 2); if (p < prev && p > best) best = p;
                    p = packvi(v.w, j0 + 3); if (p < prev && p > best) best = p;
                }
            }
            if (lane < tl) { int j = h + 4 * nv + lane; unsigned long long p = packvi(row[j], j); if (p < prev && p > best) best = p; }
            #pragma unroll
            for (int o = 16; o; o >>= 1) {
                unsigned long long q = __shfl_xor_sync(~0u, best, o);
                if (q > best) best = q;
            }
            if (lane == 0) {
                tIdx[wid][k] = 0x7FFFFFFF - (int)(best & 0xFFFFFFFFu);
                tVal[wid][k] = key2f((unsigned)(best >> 32));
            }
            prev = best;
        }
    }
    __syncwarp();

    // ---- radical features: 4 candidates concurrently, 8 lanes each ----
    const int grp = lane >> 3, gl = lane & 7;
    const float totden = 1.f / fmaxf(total, 1e-6f);
    #pragma unroll
    for (int kk = 0; kk < KTOP / 4; kk++) {
        int k = kk * 4 + grp;
        int c = tIdx[wid][k];
        const int* mrow = rmask + (size_t)c * RDIM;
        float det = 0.f; int cnt = 0;
        for (int r = gl; r < RDIM; r += 8) {
            int m = mrow[r];
            det += (float)m * rps[wid][r];
            cnt += m;
        }
        #pragma unroll
        for (int o = 4; o; o >>= 1) {
            det += __shfl_xor_sync(~0u, det, o);
            cnt += __shfl_xor_sync(~0u, cnt, o);
        }
        if (gl == 0) {
            f01[wid][k][0] = det / fmaxf((float)cnt, 1.f);
            f01[wid][k][1] = (total - det) * totden;
        }
    }
    __syncwarp();

    // ---- scalar features + MLP (one lane per candidate) ----
    float comb = 0.f;
    int myidx = 0;
    if (lane < KTOP) {
        int c = tIdx[wid][lane];
        myidx = c;
        float tv = tVal[wid][lane];
        float f0 = f01[wid][lane][0], f1 = f01[wid][lane][1];
        float f2 = sprob[wid][slab[c]];
        float f3 = fabsf((float)(sp - sclab[c])) * (1.f / 29.f);
        const float* s6 = sig + (size_t)c * STDIM;
        float n2 = 0.f, dd = 0.f;
        #pragma unroll
        for (int i = 0; i < STDIM; i++) {
            float v = s6[i];
            n2 += v * v;
            dd += predn[wid][i] * v;
        }
        float nrm = sqrtf(n2);
        float f4 = (nrm > 1e-6f) ? dd / fmaxf(nrm, 1e-12f) : 0.f;
        float f5 = __expf(tv - rowmax) * inv_sum;
        float score = 0.f;
        #pragma unroll 8
        for (int j = 0; j < HDIM; j++) {
            float hh = b1sh[j] + f0 * w1s[j] + f1 * w1s[HDIM + j]
                     + f2 * w1s[2 * HDIM + j] + f3 * w1s[3 * HDIM + j]
                     + f4 * w1s[4 * HDIM + j] + f5 * w1s[5 * HDIM + j];
            score += fmaxf(hh, 0.f) * w2sh[j];
        }
        comb = tv + s_misc[1] * (score + s_misc[0]);
    }
    __syncwarp();  // order copy-out stores before scatter (fence semantics)
    if (lane < KTOP) orow[myidx] = comb;
}

extern "C" void kernel_launch(void* const* d_in, const int* in_sizes, int n_in,
                              void* d_out, int out_size) {
    (void)n_in; (void)out_size;
    int Bn = in_sizes[0] / CDIM;
    int grid = (Bn + WPB - 1) / WPB;
    rerank_kernel<<<grid, NT>>>(
        (const float*)d_in[0],  (const float*)d_in[1],  (const float*)d_in[2],
        (const float*)d_in[3],  (const float*)d_in[4],  (const int*)d_in[5],
        (const int*)d_in[6],    (const int*)d_in[7],    (const float*)d_in[8],
        (const float*)d_in[9],  (const float*)d_in[10], (const float*)d_in[11],
        (const float*)d_in[12], (const float*)d_in[13], (float*)d_out, Bn);
}

// round 4
// speedup vs baseline: 2.0225x; 2.0225x over previous
#include <cuda_runtime.h>

#define CDIM 3755
#define RDIM 214
#define SDIM 13
#define SCBDIM 30
#define STDIM 6
#define HDIM 64
#define KTOP 20
#define CAP 512
#define NT 256
#define NEGF 3.4e38f

__device__ __forceinline__ unsigned f2key(float x) {
    unsigned u = __float_as_uint(x);
    return (u & 0x80000000u) ? ~u : (u | 0x80000000u);
}
__device__ __forceinline__ float key2f(unsigned k) {
    return __uint_as_float((k & 0x80000000u) ? (k & 0x7FFFFFFFu) : ~k);
}
__device__ __forceinline__ unsigned long long packvi(float v, int j) {
    return ((unsigned long long)f2key(v) << 32) | (unsigned)(0x7FFFFFFF - j);
}

__global__ void __launch_bounds__(NT) rerank_kernel(
    const float* __restrict__ charL, const float* __restrict__ radL,
    const float* __restrict__ structL, const float* __restrict__ scL,
    const float* __restrict__ styL, const int* __restrict__ rmask,
    const int* __restrict__ slab, const int* __restrict__ sclab,
    const float* __restrict__ sig, const float* __restrict__ W1,
    const float* __restrict__ b1, const float* __restrict__ W2,
    const float* __restrict__ b2, const float* __restrict__ rwp,
    float* __restrict__ out)
{
    __shared__ float logits[CDIM];
    __shared__ unsigned long long cpack[CAP];
    __shared__ float rps[RDIM];
    __shared__ float w1s[6 * HDIM], b1sh[HDIM], w2sh[HDIM];
    __shared__ float sprob[SDIM], predn[STDIM];
    __shared__ float feat6[KTOP][6];
    __shared__ int tIdx[KTOP];
    __shared__ float tVal[KTOP];
    __shared__ float redm[8], reds[8], redt[8];
    __shared__ unsigned long long red64[8];
    __shared__ float s_max, s_sum, s_shift, s_total, s_b2, s_rw;
    __shared__ int s_ncand, s_spred;

    const int b = blockIdx.x;
    const int tid = threadIdx.x, lane = tid & 31, wid = tid >> 5;
    const unsigned lm = (1u << lane) - 1u;

    // ---- stage weights (L2-hit loads) ----
    for (int i = tid; i < 6 * HDIM; i += NT) w1s[i] = W1[i];
    if (tid < HDIM) { b1sh[tid] = b1[tid]; w2sh[tid] = W2[tid]; }
    if (tid == 0) { s_b2 = b2[0]; s_rw = rwp[0]; }

    // ---- pass 1: row -> smem, max, unshifted expsum, radical probs ----
    const float* row = charL + (size_t)b * CDIM;
    const int h = (4 - (int)(((size_t)row >> 2) & 3)) & 3;
    const int nv = (CDIM - h) >> 2;
    const int tl = CDIM - h - 4 * nv;
    const float4* r4 = (const float4*)(row + h);

    float mx = -NEGF, se = 0.f;
    if (tid < h) { float v = row[tid]; logits[tid] = v; mx = fmaxf(mx, v); se += __expf(v); }
    for (int i = tid; i < nv; i += NT) {
        float4 v = r4[i];
        int j = h + 4 * i;
        logits[j] = v.x; logits[j + 1] = v.y; logits[j + 2] = v.z; logits[j + 3] = v.w;
        mx = fmaxf(fmaxf(fmaxf(v.x, v.y), fmaxf(v.z, v.w)), mx);
        se += __expf(v.x) + __expf(v.y) + __expf(v.z) + __expf(v.w);
    }
    if (tid < tl) {
        int j = h + 4 * nv + tid;
        float v = row[j]; logits[j] = v; mx = fmaxf(mx, v); se += __expf(v);
    }
    float tp = 0.f;
    if (tid < RDIM) {
        float p = 1.f / (1.f + __expf(-radL[(size_t)b * RDIM + tid]));
        rps[tid] = p; tp = p;
    }
    #pragma unroll
    for (int o = 16; o; o >>= 1) {
        mx = fmaxf(mx, __shfl_xor_sync(~0u, mx, o));
        se += __shfl_xor_sync(~0u, se, o);
        tp += __shfl_xor_sync(~0u, tp, o);
    }
    if (lane == 0) { redm[wid] = mx; reds[wid] = se; redt[wid] = tp; }

    // side tasks on distinct warps
    if (tid == 33) {
        const float* st = structL + (size_t)b * SDIM;
        float m = st[0]; float e[SDIM];
        for (int i = 1; i < SDIM; i++) m = fmaxf(m, st[i]);
        float s = 0.f;
        for (int i = 0; i < SDIM; i++) { e[i] = __expf(st[i] - m); s += e[i]; }
        float inv = 1.f / s;
        for (int i = 0; i < SDIM; i++) sprob[i] = e[i] * inv;
    }
    if (tid == 65) {
        const float* sc = scL + (size_t)b * SCBDIM;
        float m = sc[0]; int mi = 0;
        for (int i = 1; i < SCBDIM; i++) { float v = sc[i]; if (v > m) { m = v; mi = i; } }
        s_spred = mi;
    }
    if (tid == 97) {
        const float* sy = styL + (size_t)b * STDIM;
        float v[STDIM]; float n2 = 0.f;
        for (int i = 0; i < STDIM; i++) { v[i] = sy[i]; n2 += v[i] * v[i]; }
        float n = fmaxf(sqrtf(n2), 1e-12f);
        for (int i = 0; i < STDIM; i++) predn[i] = v[i] / n;
    }
    __syncthreads();
    if (tid == 0) {
        float m = redm[0], ss = reds[0], tt = redt[0];
        for (int w = 1; w < 8; w++) { m = fmaxf(m, redm[w]); ss += reds[w]; tt += redt[w]; }
        s_max = m; s_sum = ss; s_total = tt;
        s_shift = (m > 60.f) ? m : 0.f;
    }
    __syncthreads();
    if (s_shift != 0.f) {   // overflow-guard path; never taken for sane logits
        float se2 = 0.f;
        for (int base = 0; base < CDIM; base += NT) {
            int j = base + tid;
            if (j < CDIM) se2 += __expf(logits[j] - s_shift);
        }
        #pragma unroll
        for (int o = 16; o; o >>= 1) se2 += __shfl_xor_sync(~0u, se2, o);
        if (lane == 0) reds[wid] = se2;
        __syncthreads();
        if (tid == 0) { float ss = 0.f; for (int w = 0; w < 8; w++) ss += reds[w]; s_sum = ss; }
        __syncthreads();
    }
    const float rowmax = s_max;

    // ---- collect candidates (warp-aggregated append) ----
    float dlt = 1.2f;
    int nc;
    for (;;) {
        if (tid == 0) s_ncand = 0;
        __syncthreads();
        const float t = rowmax - dlt;
        for (int base = 0; base < CDIM; base += NT) {
            int j = base + tid;
            bool act = j < CDIM;
            float v = act ? logits[j] : -NEGF;
            bool pr = act && (v >= t);
            unsigned m = __ballot_sync(~0u, pr);
            if (m) {
                int ldr = __ffs(m) - 1;
                int bs = 0;
                if (lane == ldr) bs = atomicAdd(&s_ncand, __popc(m));
                bs = __shfl_sync(~0u, bs, ldr);
                if (pr) {
                    int pos = bs + __popc(m & lm);
                    if (pos < CAP) cpack[pos] = packvi(v, j);
                }
            }
        }
        __syncthreads();
        nc = s_ncand;
        if (nc >= KTOP) break;
        dlt *= 1.6f;
        __syncthreads();
    }

    // ---- selection ----
    if (nc <= CAP) {
        // parallel rank computation; ties: lower index wins (encoded in pack)
        unsigned long long p0 = (tid < nc) ? cpack[tid] : 0ull;
        unsigned long long p1 = (tid + NT < nc) ? cpack[tid + NT] : 0ull;
        int r0 = 0, r1 = 0;
        for (int j = 0; j < nc; j++) {
            unsigned long long q = cpack[j];
            r0 += (q > p0); r1 += (q > p1);
        }
        if (tid < nc && r0 < KTOP) {
            tIdx[r0] = 0x7FFFFFFF - (int)(p0 & 0xFFFFFFFFu);
            tVal[r0] = key2f((unsigned)(p0 >> 32));
        }
        if (tid + NT < nc && r1 < KTOP) {
            tIdx[r1] = 0x7FFFFFFF - (int)(p1 & 0xFFFFFFFFu);
            tVal[r1] = key2f((unsigned)(p1 >> 32));
        }
    } else {
        // robust fallback (adversarial data only): 20 rounds of block argmax
        for (int k = 0; k < KTOP; k++) {
            unsigned long long best = 0ull;
            for (int base = 0; base < CDIM; base += NT) {
                int j = base + tid;
                if (j < CDIM) {
                    unsigned long long p = packvi(logits[j], j);
                    if (p > best) best = p;
                }
            }
            #pragma unroll
            for (int o = 16; o; o >>= 1) {
                unsigned long long q = __shfl_xor_sync(~0u, best, o);
                if (q > best) best = q;
            }
            if (lane == 0) red64[wid] = best;
            __syncthreads();
            if (tid == 0) {
                unsigned long long m = red64[0];
                for (int w = 1; w < 8; w++) if (red64[w] > m) m = red64[w];
                int idx = 0x7FFFFFFF - (int)(m & 0xFFFFFFFFu);
                tIdx[k] = idx; tVal[k] = key2f((unsigned)(m >> 32));
                logits[idx] = -NEGF;  // exclude; overwritten by scatter later
            }
            __syncthreads();
        }
    }
    __syncthreads();

    // ---- features: 8-lane groups for radical dot; warp 5 does scalars ----
    const int g = tid >> 3, gl = tid & 7;
    const float total = s_total;
    if (g < KTOP) {
        int c = tIdx[g];
        const int2* m2 = (const int2*)(rmask + (size_t)c * RDIM);  // 856c % 8 == 0
        float det = 0.f; int cnt = 0;
        for (int r = gl; r < RDIM / 2; r += 8) {
            int2 mm = m2[r];
            det = fmaf((float)mm.x, rps[2 * r], det);
            det = fmaf((float)mm.y, rps[2 * r + 1], det);
            cnt += mm.x + mm.y;
        }
        #pragma unroll
        for (int o = 4; o; o >>= 1) {
            det += __shfl_xor_sync(~0u, det, o);
            cnt += __shfl_xor_sync(~0u, cnt, o);
        }
        if (gl == 0) {
            feat6[g][0] = det / fmaxf((float)cnt, 1.f);
            feat6[g][1] = (total - det) / fmaxf(total, 1e-6f);
        }
    }
    if (tid >= 160 && tid < 160 + KTOP) {
        int k = tid - 160;
        int c = tIdx[k];
        feat6[k][2] = sprob[slab[c]];
        feat6[k][3] = fabsf((float)(s_spred - sclab[c])) * (1.f / 29.f);
        const float* s6 = sig + (size_t)c * STDIM;
        float n2 = 0.f, dd = 0.f;
        #pragma unroll
        for (int i = 0; i < STDIM; i++) {
            float v = s6[i];
            n2 += v * v;
            dd += predn[i] * v;
        }
        float nrm = sqrtf(n2);
        feat6[k][4] = (nrm > 1e-6f) ? dd / fmaxf(nrm, 1e-12f) : 0.f;
        feat6[k][5] = __expf(tVal[k] - s_shift) / s_sum;
    }
    __syncthreads();

    // ---- MLP 6->64->1: 8-lane group per candidate, 8 units/lane ----
    if (g < KTOP) {
        float f0 = feat6[g][0], f1 = feat6[g][1], f2 = feat6[g][2];
        float f3 = feat6[g][3], f4 = feat6[g][4], f5 = feat6[g][5];
        float score = 0.f;
        #pragma unroll
        for (int u = 0; u < 8; u++) {
            int j = gl + u * 8;
            float hh = b1sh[j] + f0 * w1s[j] + f1 * w1s[HDIM + j]
                     + f2 * w1s[2 * HDIM + j] + f3 * w1s[3 * HDIM + j]
                     + f4 * w1s[4 * HDIM + j] + f5 * w1s[5 * HDIM + j];
            score += fmaxf(hh, 0.f) * w2sh[j];
        }
        #pragma unroll
        for (int o = 4; o; o >>= 1) score += __shfl_xor_sync(~0u, score, o);
        if (gl == 0) logits[tIdx[g]] = tVal[g] + s_rw * (score + s_b2);  // scatter
    }
    __syncthreads();

    // ---- stream row out (vectorized) ----
    float* orow = out + (size_t)b * CDIM;
    const int ho = (4 - (int)(((size_t)orow >> 2) & 3)) & 3;
    const int nvo = (CDIM - ho) >> 2;
    const int tlo = CDIM - ho - 4 * nvo;
    float4* o4 = (float4*)(orow + ho);
    if (tid < ho) orow[tid] = logits[tid];
    for (int i = tid; i < nvo; i += NT) {
        int j = ho + 4 * i;
        float4 w;
        w.x = logits[j]; w.y = logits[j + 1]; w.z = logits[j + 2]; w.w = logits[j + 3];
        o4[i] = w;
    }
    if (tid < tlo) { int j = ho + 4 * nvo + tid; orow[j] = logits[j]; }
}

extern "C" void kernel_launch(void* const* d_in, const int* in_sizes, int n_in,
                              void* d_out, int out_size) {
    (void)n_in; (void)out_size;
    int Bn = in_sizes[0] / CDIM;
    rerank_kernel<<<Bn, NT>>>(
        (const float*)d_in[0],  (const float*)d_in[1],  (const float*)d_in[2],
        (const float*)d_in[3],  (const float*)d_in[4],  (const int*)d_in[5],
        (const int*)d_in[6],    (const int*)d_in[7],    (const float*)d_in[8],
        (const float*)d_in[9],  (const float*)d_in[10], (const float*)d_in[11],
        (const float*)d_in[12], (const float*)d_in[13], (float*)d_out);
}